// round 11
// baseline (speedup 1.0000x reference)
#include <cuda_runtime.h>
#include <cuda_bf16.h>
#include <math.h>

#define MAXN 25600
#define IDIM 1068
#define HID  768
#define G4   3072
#define NDOCS 128
#define CBT_STRIDE 7480

// ---------------- fp32 scratch ------------------------------------------------
__device__ float d_xpad[(MAXN + 6) * IDIM];
__device__ float d_bsum[G4], d_bsumr[G4];
__device__ float d_xfeat[MAXN * HID];
__device__ float d_xpool[MAXN * HID];
__device__ float d_G[(size_t)MAXN * G4];
__device__ float d_hbuf[(MAXN + 18) * HID];
__device__ float d_cbuf[(MAXN + 18) * HID];
__device__ int   d_pos[MAXN];
__device__ int   d_off[NDOCS + 1];
__device__ unsigned d_bar;

// ---------------- bf16 (hi/lo split) scratch ----------------------------------
__device__ unsigned short h_xpad[2][(MAXN + 6) * IDIM + 8];
__device__ unsigned short h_cbt[2][3 * 256 * CBT_STRIDE];
__device__ unsigned short h_wih[2][G4 * HID];
__device__ unsigned short h_whh[2][G4 * HID];
__device__ unsigned short h_wihr[2][G4 * HID];
__device__ unsigned short h_whhr[2][G4 * HID];
__device__ unsigned short h_xfeat[2][MAXN * HID];
__device__ unsigned short h_xpool[2][MAXN * HID];
__device__ unsigned short h_hbuf[2][(MAXN + 18) * HID];

// fp32 buffer ids
#define B_XPAD  0
#define B_XFEAT 1
#define B_XPOOL 2
#define B_G     3
#define B_HBUF  4
#define B_BSUM  5
#define B_BSUMR 6

__device__ __forceinline__ float* buf_of(int id)
{
    switch (id) {
        case B_XPAD:  return d_xpad;
        case B_XFEAT: return d_xfeat;
        case B_XPOOL: return d_xpool;
        case B_G:     return d_G;
        case B_HBUF:  return d_hbuf;
        case B_BSUM:  return d_bsum;
        case B_BSUMR: return d_bsumr;
        default:      return 0;
    }
}

// bf16 buffer ids
#define H_XPAD  0
#define H_CBT   1
#define H_WIH   2
#define H_WHH   3
#define H_WIHR  4
#define H_WHHR  5
#define H_XFEAT 6
#define H_XPOOL 7
#define H_HBUF  8

__device__ __forceinline__ unsigned short* bf16_of(int id, int h)
{
    switch (id) {
        case H_XPAD:  return h_xpad[h];
        case H_CBT:   return h_cbt[h];
        case H_WIH:   return h_wih[h];
        case H_WHH:   return h_whh[h];
        case H_WIHR:  return h_wihr[h];
        case H_WHHR:  return h_whhr[h];
        case H_XFEAT: return h_xfeat[h];
        case H_XPOOL: return h_xpool[h];
        case H_HBUF:  return h_hbuf[h];
        default:      return 0;
    }
}

__device__ __forceinline__ float sigm(float x) { return 1.f / (1.f + expf(-x)); }

// packed fp32x2 helpers
__device__ __forceinline__ unsigned long long bcast2(float x)
{
    unsigned long long r;
    asm("mov.b64 %0, {%1, %1};" : "=l"(r) : "r"(__float_as_uint(x)));
    return r;
}
__device__ __forceinline__ void ffma2(unsigned long long& d,
                                      unsigned long long a, unsigned long long b)
{
    asm("fma.rn.f32x2 %0, %1, %2, %0;" : "+l"(d) : "l"(a), "l"(b));
}

// cp.async helpers
__device__ __forceinline__ unsigned smem_u32(const void* p)
{
    return (unsigned)__cvta_generic_to_shared(p);
}
__device__ __forceinline__ void cp16(unsigned s, const void* g, int src_bytes)
{
    asm volatile("cp.async.cg.shared.global [%0], [%1], 16, %2;"
                 :: "r"(s), "l"(g), "r"(src_bytes) : "memory");
}
__device__ __forceinline__ void cp8(unsigned s, const void* g, int src_bytes)
{
    asm volatile("cp.async.ca.shared.global [%0], [%1], 8, %2;"
                 :: "r"(s), "l"(g), "r"(src_bytes) : "memory");
}
__device__ __forceinline__ void cp_commit()
{
    asm volatile("cp.async.commit_group;" ::: "memory");
}
__device__ __forceinline__ void cp_wait1()
{
    asm volatile("cp.async.wait_group 1;" ::: "memory");
}

// ldmatrix helpers
__device__ __forceinline__ void ldsm4(unsigned* r, unsigned a)
{
    asm volatile("ldmatrix.sync.aligned.m8n8.x4.shared.b16 {%0,%1,%2,%3}, [%4];"
                 : "=r"(r[0]), "=r"(r[1]), "=r"(r[2]), "=r"(r[3]) : "r"(a));
}
__device__ __forceinline__ void ldsm2(unsigned* r, unsigned a)
{
    asm volatile("ldmatrix.sync.aligned.m8n8.x2.shared.b16 {%0,%1}, [%2];"
                 : "=r"(r[0]), "=r"(r[1]) : "r"(a));
}

// bf16 mma
__device__ __forceinline__ void mma16816(float* c, const unsigned* a, const unsigned* b)
{
    asm volatile(
        "mma.sync.aligned.m16n8k16.row.col.f32.bf16.bf16.f32 "
        "{%0,%1,%2,%3}, {%4,%5,%6,%7}, {%8,%9}, {%0,%1,%2,%3};"
        : "+f"(c[0]), "+f"(c[1]), "+f"(c[2]), "+f"(c[3])
        : "r"(a[0]), "r"(a[1]), "r"(a[2]), "r"(a[3]), "r"(b[0]), "r"(b[1]));
}

// ---------------- setup kernels ------------------------------------------------
__global__ void k_init(const int* __restrict__ lens)
{
    if (blockIdx.x == 0 && threadIdx.x == 0) {
        int s = 0; d_off[0] = 0;
        for (int i = 0; i < NDOCS; i++) { s += lens[i]; d_off[i + 1] = s; }
        d_bar = 0u;
    }
}

__global__ void k_pos(int N)
{
    int n = blockIdx.x * blockDim.x + threadIdx.x;
    if (n >= N) return;
    int lo = 0, hi = NDOCS;
    while (hi - lo > 1) { int mid = (lo + hi) >> 1; if (d_off[mid] <= n) lo = mid; else hi = mid; }
    d_pos[n] = n - d_off[lo];
}

__global__ void k_xpad(const float* __restrict__ x, int N)
{
    int idx = blockIdx.x * blockDim.x + threadIdx.x;
    int total = (N + 6) * IDIM;
    if (idx >= total) return;
    int r = idx / IDIM, dd = idx % IDIM;
    if (r < 3 || r >= N + 3) { d_xpad[idx] = 0.f; return; }
    int n = r - 3;
    int p = d_pos[n];
    int i = dd >> 1;
    float denom = powf(10000.f, (2.f * (float)i) / 1068.f);
    float ang = (float)p / denom;
    float pe = (dd & 1) ? cosf(ang) : sinf(ang);
    d_xpad[idx] = x[(size_t)n * IDIM + dd] + pe;
}

__global__ void k_split(int srcId, int dstId, int n)
{
    int i = blockIdx.x * blockDim.x + threadIdx.x;
    if (i >= n) return;
    float v = buf_of(srcId)[i];
    __nv_bfloat16 hb = __float2bfloat16(v);
    float r = v - __bfloat162float(hb);
    bf16_of(dstId, 0)[i] = __bfloat16_as_ushort(hb);
    bf16_of(dstId, 1)[i] = __bfloat16_as_ushort(__float2bfloat16(r));
}

__global__ void k_splitW(const float* __restrict__ src, int dstId, int n)
{
    int i = blockIdx.x * blockDim.x + threadIdx.x;
    if (i >= n) return;
    float v = src[i];
    __nv_bfloat16 hb = __float2bfloat16(v);
    float r = v - __bfloat162float(hb);
    bf16_of(dstId, 0)[i] = __bfloat16_as_ushort(hb);
    bf16_of(dstId, 1)[i] = __bfloat16_as_ushort(__float2bfloat16(r));
}

__global__ void k_tconv2(const float* __restrict__ w, int k, int Ks, int c)
{
    int idx = blockIdx.x * blockDim.x + threadIdx.x;
    int total = 256 * Ks;
    if (idx >= total) return;
    int oc = idx / Ks, col = idx % Ks;
    float v = 0.f;
    if (col < k * IDIM) {
        int j = col / IDIM, d = col % IDIM;
        v = w[(size_t)oc * IDIM * k + (size_t)d * k + j];
    }
    __nv_bfloat16 hb = __float2bfloat16(v);
    float r = v - __bfloat162float(hb);
    size_t o = (size_t)c * 256 * CBT_STRIDE + idx;
    h_cbt[0][o] = __bfloat16_as_ushort(hb);
    h_cbt[1][o] = __bfloat16_as_ushort(__float2bfloat16(r));
}

__global__ void k_bsum(const float* __restrict__ a, const float* __restrict__ b, int dstId)
{
    int i = blockIdx.x * blockDim.x + threadIdx.x;
    if (i < G4) buf_of(dstId)[i] = a[i] + b[i];
}

__global__ void k_pool(int N)
{
    int idx = blockIdx.x * blockDim.x + threadIdx.x;
    if (idx >= N * HID) return;
    int n = idx / HID, f = idx % HID;
    int p = (f < 256) ? 1 : ((f < 512) ? 2 : 3);
    int lo = n - p; if (lo < 0) lo = 0;
    int hi = n + p; if (hi > N - 1) hi = N - 1;
    float v = -INFINITY;
    for (int m = lo; m <= hi; m++) {
        float u = d_xfeat[(size_t)m * HID + f];
        v = (u > v) ? u : v;
    }
    d_xpool[idx] = v;
}

__global__ void k_zero_hc(int N)
{
    int idx = blockIdx.x * blockDim.x + threadIdx.x;
    if (idx >= 18 * HID) return;
    int i = idx / HID, ch = idx % HID;
    int row = (i < 9) ? i : (N + i);
    d_hbuf[(size_t)row * HID + ch] = 0.f;
    d_cbuf[(size_t)row * HID + ch] = 0.f;
}

// ---------------- bf16 tensor-core GEMM (ldmatrix) -----------------------------
// C[M,Nn] (=|+=) 3-pass split GEMM: Ah@Bh + Ah@Bl + Al@Bh
// A: [M,K] bf16 row-major (lda elems). B: [Nn,K] bf16 row-major (ldbt elems) == B^T.
__global__ void __launch_bounds__(256, 2) gemm16_k(
    int aid, size_t aoff, int lda,
    int bid, size_t boff, int ldbt,
    int cid, size_t coff, int ldc,
    int M, int Nn, int K, int Ks,
    const float* __restrict__ bias_ext, int bias_id, int accflag, int leakyflag)
{
    const unsigned short* Ah = bf16_of(aid, 0) + aoff;
    const unsigned short* Al = bf16_of(aid, 1) + aoff;
    const unsigned short* Bh = bf16_of(bid, 0) + boff;
    const unsigned short* Bl = bf16_of(bid, 1) + boff;
    float* C = buf_of(cid) + coff;
    const float* bias = (bias_id >= 0) ? buf_of(bias_id) : bias_ext;

    __shared__ __align__(16) unsigned As[2][2560];
    __shared__ __align__(16) unsigned Bs2[2][2560];

    const int tid = threadIdx.x;
    const int warp = tid >> 5, lane = tid & 31;
    const int g = lane >> 2, t = lane & 3;
    const int wm0 = (warp >> 2) * 64, wn0 = (warp & 3) * 32;
    const int bm = blockIdx.y * 128, bn = blockIdx.x * 128;

    float acc[4][4][4];
#pragma unroll
    for (int i = 0; i < 4; i++)
#pragma unroll
        for (int j = 0; j < 4; j++)
#pragma unroll
            for (int e = 0; e < 4; e++) acc[i][j][e] = 0.f;

    const int S = (Ks + 31) / 32;
    const unsigned aS0 = smem_u32(&As[0][0]);
    const unsigned aS1 = smem_u32(&As[1][0]);
    const unsigned bS0 = smem_u32(&Bs2[0][0]);
    const unsigned bS1 = smem_u32(&Bs2[1][0]);
    // ldmatrix per-lane row offsets
    const int arow = (lane & 15) * 80 + (lane >> 4) * 16;
    const int brow = (lane & 7) * 80 + ((lane >> 3) & 1) * 16;

    for (int pass = 0; pass < 3; ++pass) {
        const unsigned short* Ap = (pass == 2) ? Al : Ah;
        const unsigned short* Bp = (pass == 1) ? Bl : Bh;

        // prologue: slice 0 -> buf 0
        {
#pragma unroll
            for (int i = 0; i < 4; i++) {
                int v = tid + 256 * i;
                int row = v >> 3, ch = v & 7;
                int gk = ch * 4;
                int rem = (bm + row < M) ? (K - gk) : 0;
                int bytes = rem >= 4 ? 8 : 0;
                const void* src = bytes ? (const void*)(Ap + (size_t)(bm + row) * lda + gk)
                                        : (const void*)Ap;
                cp8(aS0 + row * 80 + ch * 8, src, bytes);
            }
#pragma unroll
            for (int i = 0; i < 2; i++) {
                int v = tid + 256 * i;
                int row = v >> 2, ch = v & 3;
                int gk = ch * 8;
                int rem = Ks - gk;
                int bytes = rem >= 8 ? 16 : 0;
                const void* src = bytes ? (const void*)(Bp + (size_t)(bn + row) * ldbt + gk)
                                        : (const void*)Bp;
                cp16(bS0 + row * 80 + ch * 16, src, bytes);
            }
            cp_commit();
        }

        for (int s = 0; s < S; ++s) {
            const int buf = s & 1;
            if (s + 1 < S) {
                int k0 = (s + 1) * 32;
                unsigned aD = buf ? aS0 : aS1;
                unsigned bD = buf ? bS0 : bS1;
#pragma unroll
                for (int i = 0; i < 4; i++) {
                    int v = tid + 256 * i;
                    int row = v >> 3, ch = v & 7;
                    int gk = k0 + ch * 4;
                    int rem = (bm + row < M) ? (K - gk) : 0;
                    int bytes = rem >= 4 ? 8 : 0;
                    const void* src = bytes ? (const void*)(Ap + (size_t)(bm + row) * lda + gk)
                                            : (const void*)Ap;
                    cp8(aD + row * 80 + ch * 8, src, bytes);
                }
#pragma unroll
                for (int i = 0; i < 2; i++) {
                    int v = tid + 256 * i;
                    int row = v >> 2, ch = v & 3;
                    int gk = k0 + ch * 8;
                    int rem = Ks - gk;
                    int bytes = rem >= 8 ? 16 : 0;
                    const void* src = bytes ? (const void*)(Bp + (size_t)(bn + row) * ldbt + gk)
                                            : (const void*)Bp;
                    cp16(bD + row * 80 + ch * 16, src, bytes);
                }
            }
            cp_commit();
            cp_wait1();
            __syncthreads();

            const unsigned aBuf = buf ? aS1 : aS0;
            const unsigned bBuf = buf ? bS1 : bS0;
#pragma unroll
            for (int kh = 0; kh < 2; kh++) {
                unsigned af[4][4], bfr[4][2];
#pragma unroll
                for (int mt = 0; mt < 4; mt++)
                    ldsm4(af[mt], aBuf + (wm0 + mt * 16) * 80 + kh * 32 + arow);
#pragma unroll
                for (int nt = 0; nt < 4; nt++)
                    ldsm2(bfr[nt], bBuf + (wn0 + nt * 8) * 80 + kh * 32 + brow);
#pragma unroll
                for (int mt = 0; mt < 4; mt++)
#pragma unroll
                    for (int nt = 0; nt < 4; nt++)
                        mma16816(acc[mt][nt], af[mt], bfr[nt]);
            }
            __syncthreads();
        }
    }

    // epilogue
#pragma unroll
    for (int mt = 0; mt < 4; mt++) {
        int r0 = bm + wm0 + mt * 16 + g;
#pragma unroll
        for (int nt = 0; nt < 4; nt++) {
            int c0 = bn + wn0 + nt * 8 + 2 * t;
#pragma unroll
            for (int e = 0; e < 4; e++) {
                int rr = r0 + (e >> 1) * 8;
                int cc = c0 + (e & 1);
                if (rr < M) {
                    float v = acc[mt][nt][e];
                    float* p = C + (size_t)rr * ldc + cc;
                    if (accflag) {
                        *p += v;
                    } else {
                        v += bias ? bias[cc] : 0.f;
                        if (leakyflag) v = (v >= 0.f) ? v : 0.01f * v;
                        *p = v;
                    }
                }
            }
        }
    }
}

// ---------------- persistent chunked-LSTM scan (FFMA2) ------------------------
// 128 blocks, 6 h-columns each. Warp layout: wg=warp>>1 -> rows 4wg..4wg+3,
// pg=warp&1 -> 12 (gate,col) pairs. h chunk pair-packed in smem for LDS.64.
#define SCAN_NB 128
#define COLS_PB 6

__global__ void __launch_bounds__(256) scan_k(const float* __restrict__ Whh,
                                              int N, int n_chunks)
{
    extern __shared__ float sh[];   // pair-packed h: word ((r>>1)*768+f)*2+(r&1); 49152 B
    unsigned long long* sh64 = (unsigned long long*)sh;
    const int tid = threadIdx.x;
    const int lane = tid & 31, warp = tid >> 5;
    const int wg = warp >> 1;        // rows 4wg .. 4wg+3 (pair rows 2wg, 2wg+1)
    const int pg = warp & 1;         // pairs 12pg .. 12pg+11
    const int colBase = blockIdx.x * COLS_PB;
    unsigned target = 0;

    const float* wrow[12];
#pragma unroll
    for (int p = 0; p < 12; p++) {
        int pp = pg * 12 + p;
        int gate = pp / COLS_PB, cl = pp % COLS_PB;
        wrow[p] = Whh + (size_t)(gate * HID + colBase + cl) * HID;
    }

    for (int t = 0; t < n_chunks; ++t) {
        // load h chunk (rows (t-1)*16..+15) pair-packed into smem
        if (t == 0) {
            for (int i = tid; i < 8 * HID; i += 256) sh64[i] = 0ull;
        } else {
            const float* src = d_hbuf + (size_t)(9 + (t - 1) * 16) * HID;
            for (int i = tid; i < 8 * HID; i += 256) {
                int p2 = i / HID, f = i % HID;
                float lo = __ldcg(src + (size_t)(2 * p2) * HID + f);
                float hi = __ldcg(src + (size_t)(2 * p2 + 1) * HID + f);
                unsigned long long u;
                asm("mov.b64 %0, {%1, %2};" : "=l"(u)
                    : "r"(__float_as_uint(lo)), "r"(__float_as_uint(hi)));
                sh64[(size_t)p2 * HID + f] = u;
            }
        }
        __syncthreads();

        unsigned long long acc2[12][2];
#pragma unroll
        for (int p = 0; p < 12; p++) { acc2[p][0] = 0ull; acc2[p][1] = 0ull; }

        const unsigned long long* shp0 = sh64 + (size_t)(2 * wg) * HID;
        const unsigned long long* shp1 = shp0 + HID;
#pragma unroll 2
        for (int it = 0; it < 24; ++it) {
            int f = lane + 32 * it;
            unsigned long long h0 = shp0[f];
            unsigned long long h1 = shp1[f];
#pragma unroll
            for (int p = 0; p < 12; p++) {
                unsigned long long a = bcast2(__ldg(wrow[p] + f));
                ffma2(acc2[p][0], a, h0);
                ffma2(acc2[p][1], a, h1);
            }
        }
        __syncthreads();   // done reading h; reuse sh[0..383] as gate staging

#pragma unroll
        for (int p = 0; p < 12; p++) {
            int pp = pg * 12 + p;
            int gate = pp / COLS_PB, cl = pp % COLS_PB;
#pragma unroll
            for (int q = 0; q < 2; q++) {
                float vlo = __uint_as_float((unsigned)acc2[p][q]);
                float vhi = __uint_as_float((unsigned)(acc2[p][q] >> 32));
#pragma unroll
                for (int s = 16; s >= 1; s >>= 1) {
                    vlo += __shfl_down_sync(0xffffffffu, vlo, s);
                    vhi += __shfl_down_sync(0xffffffffu, vhi, s);
                }
                if (lane == 0) {
                    int r0 = 4 * wg + 2 * q;
                    sh[(cl * 4 + gate) * 16 + r0]     = vlo;
                    sh[(cl * 4 + gate) * 16 + r0 + 1] = vhi;
                }
            }
        }
        __syncthreads();

        if (tid < 16 * COLS_PB) {
            int r = tid & 15, cl = tid >> 4;
            int n = t * 16 + r;
            if (n < N) {
                int col = colBase + cl;
                const float* gq = d_G + (size_t)n * G4;
                float gi = gq[col]        + sh[(cl * 4 + 0) * 16 + r];
                float gf = gq[col + 768]  + sh[(cl * 4 + 1) * 16 + r];
                float gg = gq[col + 1536] + sh[(cl * 4 + 2) * 16 + r];
                float go = gq[col + 2304] + sh[(cl * 4 + 3) * 16 + r];
                float cp = (t == 0) ? 0.f : d_cbuf[(size_t)(9 + n - 16) * HID + col];
                float c2 = sigm(gf) * cp + sigm(gi) * tanhf(gg);
                d_hbuf[(size_t)(9 + n) * HID + col] = sigm(go) * tanhf(c2);
                d_cbuf[(size_t)(9 + n) * HID + col] = c2;
            }
        }
        __threadfence();
        __syncthreads();
        target += gridDim.x;
        if (tid == 0) {
            atomicAdd(&d_bar, 1u);
            while (*((volatile unsigned*)&d_bar) < target) { __nanosleep(20); }
        }
        __syncthreads();
        __threadfence();
    }
}

// ---------------- final LSTM cell epilogue ------------------------------------
__global__ void k_final(float* __restrict__ out, int N, int rev)
{
    int idx = blockIdx.x * blockDim.x + threadIdx.x;
    if (idx >= N * HID) return;
    int n = idx / HID, ch = idx % HID;
    const float* g = d_G + (size_t)n * G4;
    float gi = sigm(g[ch]);
    float gf = sigm(g[ch + 768]);
    float gg = tanhf(g[ch + 1536]);
    float go = sigm(g[ch + 2304]);
    float cp = d_cbuf[(size_t)(n + (rev ? 18 : 0)) * HID + ch];
    float c2 = gf * cp + gi * gg;
    out[(size_t)n * 1536 + (rev ? 768 : 0) + ch] = go * tanhf(c2);
}

// ---------------- host side ---------------------------------------------------
static inline int ceil_div(int a, int b) { return (a + b - 1) / b; }

static void gemm16(int aid, size_t aoff, int lda, int bid, size_t boff, int ldbt,
                   int cid, size_t coff, int ldc, int M, int Nn, int K, int Ks,
                   const float* bias_ext, int bias_id, int acc, int leaky = 0)
{
    dim3 g(Nn / 128, ceil_div(M, 128));
    gemm16_k<<<g, 256>>>(aid, aoff, lda, bid, boff, ldbt, cid, coff, ldc,
                         M, Nn, K, Ks, bias_ext, bias_id, acc, leaky);
}

extern "C" void kernel_launch(void* const* d_in, const int* in_sizes, int n_in,
                              void* d_out, int out_size)
{
    const float* x      = (const float*)d_in[0];
    const int*   lens   = (const int*)d_in[1];
    const float* cw[3]  = {(const float*)d_in[2], (const float*)d_in[4], (const float*)d_in[6]};
    const float* cb[3]  = {(const float*)d_in[3], (const float*)d_in[5], (const float*)d_in[7]};
    const float* W_ih   = (const float*)d_in[8];
    const float* W_hh   = (const float*)d_in[9];
    const float* b_ih   = (const float*)d_in[10];
    const float* b_hh   = (const float*)d_in[11];
    const float* W_ihr  = (const float*)d_in[12];
    const float* W_hhr  = (const float*)d_in[13];
    const float* b_ihr  = (const float*)d_in[14];
    const float* b_hhr  = (const float*)d_in[15];
    float* out = (float*)d_out;

    const int N = out_size / 1536;
    const int n_chunks = (N + 15) / 16;

    k_init<<<1, 32>>>(lens);
    k_pos<<<ceil_div(N, 256), 256>>>(N);
    k_xpad<<<ceil_div((N + 6) * IDIM, 256), 256>>>(x, N);
    k_split<<<ceil_div((N + 6) * IDIM, 256), 256>>>(B_XPAD, H_XPAD, (N + 6) * IDIM);

    const int ks[3] = {3, 5, 7};
    int Ksv[3];
    for (int c = 0; c < 3; c++) {
        int K = ks[c] * IDIM;
        Ksv[c] = (K + 7) & ~7;
        k_tconv2<<<ceil_div(256 * Ksv[c], 256), 256>>>(cw[c], ks[c], Ksv[c], c);
    }
    k_splitW<<<ceil_div(G4 * HID, 256), 256>>>(W_ih,  H_WIH,  G4 * HID);
    k_splitW<<<ceil_div(G4 * HID, 256), 256>>>(W_hh,  H_WHH,  G4 * HID);
    k_splitW<<<ceil_div(G4 * HID, 256), 256>>>(W_ihr, H_WIHR, G4 * HID);
    k_splitW<<<ceil_div(G4 * HID, 256), 256>>>(W_hhr, H_WHHR, G4 * HID);
    k_bsum<<<ceil_div(G4, 256), 256>>>(b_ih,  b_hh,  B_BSUM);
    k_bsum<<<ceil_div(G4, 256), 256>>>(b_ihr, b_hhr, B_BSUMR);

    // conv: one tensor GEMM per kernel size; bias + LeakyReLU fused
    for (int c = 0; c < 3; c++) {
        int k = ks[c], p = k / 2, chOff = 256 * c;
        gemm16(H_XPAD, (size_t)(3 - p) * IDIM, IDIM,
               H_CBT, (size_t)c * 256 * CBT_STRIDE, Ksv[c],
               B_XFEAT, (size_t)chOff, HID,
               N, 256, k * IDIM, Ksv[c],
               cb[c], -1, 0, /*leaky=*/1);
    }
    k_pool<<<ceil_div(N * HID, 256), 256>>>(N);
    k_split<<<ceil_div(N * HID, 256), 256>>>(B_XFEAT, H_XFEAT, N * HID);
    k_split<<<ceil_div(N * HID, 256), 256>>>(B_XPOOL, H_XPOOL, N * HID);

    // scan gates x-part: G = xpool @ W_ih^T + (b_ih + b_hh)
    gemm16(H_XPOOL, 0, HID, H_WIH, 0, HID, B_G, 0, G4, N, G4, HID, HID, 0, B_BSUM, 0);
    k_zero_hc<<<ceil_div(18 * HID, 256), 256>>>(N);
    scan_k<<<SCAN_NB, 256, 16 * HID * sizeof(float)>>>(W_hh, N, n_chunks);
    k_split<<<ceil_div((N + 18) * HID, 256), 256>>>(B_HBUF, H_HBUF, (N + 18) * HID);

    // forward final cell
    gemm16(H_XFEAT, 0, HID, H_WIH, 0, HID, B_G, 0, G4, N, G4, HID, HID, 0, B_BSUM, 0);
    gemm16(H_HBUF, 0, HID, H_WHH, 0, HID, B_G, 0, G4, N, G4, HID, HID, 0, -1, 1);
    k_final<<<ceil_div(N * HID, 256), 256>>>(out, N, 0);

    // reverse final cell
    gemm16(H_XFEAT, 0, HID, H_WIHR, 0, HID, B_G, 0, G4, N, G4, HID, HID, 0, B_BSUMR, 0);
    gemm16(H_HBUF, (size_t)18 * HID, HID, H_WHHR, 0, HID, B_G, 0, G4, N, G4, HID, HID, 0, -1, 1);
    k_final<<<ceil_div(N * HID, 256), 256>>>(out, N, 1);
}

// round 12
// speedup vs baseline: 1.1281x; 1.1281x over previous
#include <cuda_runtime.h>
#include <cuda_bf16.h>
#include <math.h>

#define MAXN 25600
#define IDIM 1068
#define HID  768
#define G4   3072
#define NDOCS 128
#define CBT_STRIDE 7480

// ---------------- fp32 scratch ------------------------------------------------
__device__ __align__(16) float d_xpad[(MAXN + 6) * IDIM];
__device__ float d_bsum[G4], d_bsumr[G4];
__device__ __align__(16) float d_xfeat[MAXN * HID];
__device__ __align__(16) float d_xpool[MAXN * HID];
__device__ __align__(16) float d_G[(size_t)MAXN * G4];
__device__ __align__(16) float d_hbuf[(MAXN + 18) * HID];
__device__ __align__(16) float d_cbuf[(MAXN + 18) * HID];
__device__ int   d_pos[MAXN];
__device__ int   d_off[NDOCS + 1];
__device__ unsigned d_bar;

// ---------------- bf16 (hi/lo split) scratch ----------------------------------
__device__ __align__(16) unsigned short h_xpad[2][(MAXN + 6) * IDIM + 8];
__device__ __align__(16) unsigned short h_cbt[2][3 * 256 * CBT_STRIDE];
__device__ __align__(16) unsigned short h_wih[2][G4 * HID];
__device__ __align__(16) unsigned short h_xpool[2][MAXN * HID];
__device__ __align__(16) unsigned short h_fza[2][(size_t)MAXN * 1536];  // [xfeat | h_prev]
__device__ __align__(16) unsigned short h_fzr[2][(size_t)MAXN * 1536];  // [xfeat | h_next]
__device__ __align__(16) unsigned short h_wfz[2][G4 * 1536];            // [Wih | Whh]
__device__ __align__(16) unsigned short h_wfzr[2][G4 * 1536];           // [Wihr | Whhr]

// fp32 buffer ids
#define B_XPAD  0
#define B_XFEAT 1
#define B_XPOOL 2
#define B_G     3
#define B_BSUM  4
#define B_BSUMR 5

__device__ __forceinline__ float* buf_of(int id)
{
    switch (id) {
        case B_XPAD:  return d_xpad;
        case B_XFEAT: return d_xfeat;
        case B_XPOOL: return d_xpool;
        case B_G:     return d_G;
        case B_BSUM:  return d_bsum;
        case B_BSUMR: return d_bsumr;
        default:      return 0;
    }
}

// bf16 buffer ids
#define H_XPAD  0
#define H_CBT   1
#define H_WIH   2
#define H_XPOOL 3
#define H_FZF   4
#define H_FZR   5
#define H_WFZ   6
#define H_WFZR  7

__device__ __forceinline__ unsigned short* bf16_of(int id, int h)
{
    switch (id) {
        case H_XPAD:  return h_xpad[h];
        case H_CBT:   return h_cbt[h];
        case H_WIH:   return h_wih[h];
        case H_XPOOL: return h_xpool[h];
        case H_FZF:   return h_fza[h];
        case H_FZR:   return h_fzr[h];
        case H_WFZ:   return h_wfz[h];
        case H_WFZR:  return h_wfzr[h];
        default:      return 0;
    }
}

__device__ __forceinline__ float sigm(float x) { return 1.f / (1.f + expf(-x)); }

__device__ __forceinline__ void split1(float v, unsigned short& hi, unsigned short& lo)
{
    __nv_bfloat16 hb = __float2bfloat16(v);
    hi = __bfloat16_as_ushort(hb);
    lo = __bfloat16_as_ushort(__float2bfloat16(v - __bfloat162float(hb)));
}

// cp.async helpers
__device__ __forceinline__ unsigned smem_u32(const void* p)
{
    return (unsigned)__cvta_generic_to_shared(p);
}
__device__ __forceinline__ void cp16(unsigned s, const void* g, int src_bytes)
{
    asm volatile("cp.async.cg.shared.global [%0], [%1], 16, %2;"
                 :: "r"(s), "l"(g), "r"(src_bytes) : "memory");
}
__device__ __forceinline__ void cp8(unsigned s, const void* g, int src_bytes)
{
    asm volatile("cp.async.ca.shared.global [%0], [%1], 8, %2;"
                 :: "r"(s), "l"(g), "r"(src_bytes) : "memory");
}
__device__ __forceinline__ void cp_commit()
{
    asm volatile("cp.async.commit_group;" ::: "memory");
}
__device__ __forceinline__ void cp_wait1()
{
    asm volatile("cp.async.wait_group 1;" ::: "memory");
}

// bf16 mma
__device__ __forceinline__ void mma16816(float* c, const unsigned* a, const unsigned* b)
{
    asm volatile(
        "mma.sync.aligned.m16n8k16.row.col.f32.bf16.bf16.f32 "
        "{%0,%1,%2,%3}, {%4,%5,%6,%7}, {%8,%9}, {%0,%1,%2,%3};"
        : "+f"(c[0]), "+f"(c[1]), "+f"(c[2]), "+f"(c[3])
        : "r"(a[0]), "r"(a[1]), "r"(a[2]), "r"(a[3]), "r"(b[0]), "r"(b[1]));
}

// ---------------- setup kernels ------------------------------------------------
__global__ void k_init(const int* __restrict__ lens)
{
    if (blockIdx.x == 0 && threadIdx.x == 0) {
        int s = 0; d_off[0] = 0;
        for (int i = 0; i < NDOCS; i++) { s += lens[i]; d_off[i + 1] = s; }
        d_bar = 0u;
    }
}

__global__ void k_pos(int N)
{
    int n = blockIdx.x * blockDim.x + threadIdx.x;
    if (n >= N) return;
    int lo = 0, hi = NDOCS;
    while (hi - lo > 1) { int mid = (lo + hi) >> 1; if (d_off[mid] <= n) lo = mid; else hi = mid; }
    d_pos[n] = n - d_off[lo];
}

__global__ void k_xpad(const float* __restrict__ x, int N)
{
    int idx = blockIdx.x * blockDim.x + threadIdx.x;
    int total = (N + 6) * IDIM;
    if (idx >= total) return;
    int r = idx / IDIM, dd = idx % IDIM;
    if (r < 3 || r >= N + 3) { d_xpad[idx] = 0.f; return; }
    int n = r - 3;
    int p = d_pos[n];
    int i = dd >> 1;
    float denom = powf(10000.f, (2.f * (float)i) / 1068.f);
    float ang = (float)p / denom;
    float pe = (dd & 1) ? cosf(ang) : sinf(ang);
    d_xpad[idx] = x[(size_t)n * IDIM + dd] + pe;
}

// vectorized split: 4 elems/thread, simple dst layout
__global__ void k_split4(int srcId, int dstId, int n4)
{
    int i = blockIdx.x * blockDim.x + threadIdx.x;
    if (i >= n4) return;
    float4 v = *(const float4*)(buf_of(srcId) + (size_t)i * 4);
    ushort4 hi, lo;
    split1(v.x, hi.x, lo.x); split1(v.y, hi.y, lo.y);
    split1(v.z, hi.z, lo.z); split1(v.w, hi.w, lo.w);
    *(ushort4*)(bf16_of(dstId, 0) + (size_t)i * 4) = hi;
    *(ushort4*)(bf16_of(dstId, 1) + (size_t)i * 4) = lo;
}

// xfeat -> cols [0,768) of BOTH fused A buffers
__global__ void k_split_xf4(int n4)
{
    int i = blockIdx.x * blockDim.x + threadIdx.x;
    if (i >= n4) return;
    int e = i * 4;
    int n = e / HID, ch = e % HID;
    float4 v = *(const float4*)(d_xfeat + (size_t)e);
    ushort4 hi, lo;
    split1(v.x, hi.x, lo.x); split1(v.y, hi.y, lo.y);
    split1(v.z, hi.z, lo.z); split1(v.w, hi.w, lo.w);
    size_t o = (size_t)n * 1536 + ch;
    *(ushort4*)(h_fza[0] + o) = hi;  *(ushort4*)(h_fza[1] + o) = lo;
    *(ushort4*)(h_fzr[0] + o) = hi;  *(ushort4*)(h_fzr[1] + o) = lo;
}

// h -> cols [768,1536): fwd uses hbuf row n (= h[n-9]); rev uses hbuf row n+18 (= h[n+9])
__global__ void k_split_h4(int n4)
{
    int i = blockIdx.x * blockDim.x + threadIdx.x;
    if (i >= n4) return;
    int e = i * 4;
    int n = e / HID, ch = e % HID;
    float4 vf = *(const float4*)(d_hbuf + (size_t)n * HID + ch);
    float4 vr = *(const float4*)(d_hbuf + (size_t)(n + 18) * HID + ch);
    ushort4 hf, lf, hr, lr;
    split1(vf.x, hf.x, lf.x); split1(vf.y, hf.y, lf.y);
    split1(vf.z, hf.z, lf.z); split1(vf.w, hf.w, lf.w);
    split1(vr.x, hr.x, lr.x); split1(vr.y, hr.y, lr.y);
    split1(vr.z, hr.z, lr.z); split1(vr.w, hr.w, lr.w);
    size_t o = (size_t)n * 1536 + 768 + ch;
    *(ushort4*)(h_fza[0] + o) = hf;  *(ushort4*)(h_fza[1] + o) = lf;
    *(ushort4*)(h_fzr[0] + o) = hr;  *(ushort4*)(h_fzr[1] + o) = lr;
}

// one launch: fused LSTM weights + standalone Wih + biases + conv weight planes
#define KSV0 3208
#define KSV1 5344
#define KSV2 7480
__global__ void k_prepw(const float* __restrict__ W_ih, const float* __restrict__ W_hh,
                        const float* __restrict__ W_ihr, const float* __restrict__ W_hhr,
                        const float* __restrict__ b_ih, const float* __restrict__ b_hh,
                        const float* __restrict__ b_ihr, const float* __restrict__ b_hhr,
                        const float* __restrict__ cw0, const float* __restrict__ cw1,
                        const float* __restrict__ cw2)
{
    int idx = blockIdx.x * blockDim.x + threadIdx.x;
    if (idx < G4 * 1536) {
        int g = idx / 1536, c = idx % 1536;
        float vf = (c < HID) ? W_ih[(size_t)g * HID + c] : W_hh[(size_t)g * HID + c - HID];
        float vr = (c < HID) ? W_ihr[(size_t)g * HID + c] : W_hhr[(size_t)g * HID + c - HID];
        unsigned short a, b;
        split1(vf, a, b); h_wfz[0][idx] = a; h_wfz[1][idx] = b;
        split1(vr, a, b); h_wfzr[0][idx] = a; h_wfzr[1][idx] = b;
        if (c < HID) {
            split1(vf, a, b);
            h_wih[0][(size_t)g * HID + c] = a;
            h_wih[1][(size_t)g * HID + c] = b;
        }
    }
    if (idx < G4) {
        d_bsum[idx]  = b_ih[idx]  + b_hh[idx];
        d_bsumr[idx] = b_ihr[idx] + b_hhr[idx];
    }
    // conv planes: [c][oc][col] col = j*IDIM + d, rows padded to Ksv
    const int C0 = 256 * KSV0, C1 = C0 + 256 * KSV1, C2 = C1 + 256 * KSV2;
    if (idx < C2) {
        int c, local, Ks, kk;
        const float* w;
        if (idx < C0)      { c = 0; local = idx;      Ks = KSV0; kk = 3; w = cw0; }
        else if (idx < C1) { c = 1; local = idx - C0; Ks = KSV1; kk = 5; w = cw1; }
        else               { c = 2; local = idx - C1; Ks = KSV2; kk = 7; w = cw2; }
        int oc = local / Ks, col = local % Ks;
        float v = 0.f;
        if (col < kk * IDIM) {
            int j = col / IDIM, d = col % IDIM;
            v = w[(size_t)oc * IDIM * kk + (size_t)d * kk + j];
        }
        unsigned short a, b;
        split1(v, a, b);
        size_t o = (size_t)c * 256 * CBT_STRIDE + (size_t)oc * Ks + col;
        h_cbt[0][o] = a; h_cbt[1][o] = b;
    }
}

__global__ void k_pool(int N)
{
    int idx = blockIdx.x * blockDim.x + threadIdx.x;
    if (idx >= N * HID) return;
    int n = idx / HID, f = idx % HID;
    int p = (f < 256) ? 1 : ((f < 512) ? 2 : 3);
    int lo = n - p; if (lo < 0) lo = 0;
    int hi = n + p; if (hi > N - 1) hi = N - 1;
    float v = -INFINITY;
    for (int m = lo; m <= hi; m++) {
        float u = d_xfeat[(size_t)m * HID + f];
        v = (u > v) ? u : v;
    }
    d_xpool[idx] = v;
}

__global__ void k_zero_hc(int N)
{
    int idx = blockIdx.x * blockDim.x + threadIdx.x;
    if (idx >= 18 * HID) return;
    int i = idx / HID, ch = idx % HID;
    int row = (i < 9) ? i : (N + i);
    d_hbuf[(size_t)row * HID + ch] = 0.f;
    d_cbuf[(size_t)row * HID + ch] = 0.f;
}

// ---------------- bf16 tensor-core GEMM (round-9 proven version) ---------------
// C[M,Nn] = 3-pass split GEMM: Ah@Bh + Ah@Bl + Al@Bh (+bias, optional leaky)
// A: [M,K] bf16 row-major (lda elems). B: [Nn,K] bf16 row-major (ldbt elems).
__global__ void __launch_bounds__(256, 2) gemm16_k(
    int aid, size_t aoff, int lda,
    int bid, size_t boff, int ldbt,
    int cid, size_t coff, int ldc,
    int M, int Nn, int K, int Ks,
    const float* __restrict__ bias_ext, int bias_id, int accflag, int leakyflag)
{
    const unsigned short* Ah = bf16_of(aid, 0) + aoff;
    const unsigned short* Al = bf16_of(aid, 1) + aoff;
    const unsigned short* Bh = bf16_of(bid, 0) + boff;
    const unsigned short* Bl = bf16_of(bid, 1) + boff;
    float* C = buf_of(cid) + coff;
    const float* bias = (bias_id >= 0) ? buf_of(bias_id) : bias_ext;

    __shared__ __align__(16) unsigned As[2][2560];
    __shared__ __align__(16) unsigned Bs2[2][2560];

    const int tid = threadIdx.x;
    const int warp = tid >> 5, lane = tid & 31;
    const int g = lane >> 2, t = lane & 3;
    const int wm0 = (warp >> 2) * 64, wn0 = (warp & 3) * 32;
    const int bm = blockIdx.y * 128, bn = blockIdx.x * 128;

    float acc[4][4][4];
#pragma unroll
    for (int i = 0; i < 4; i++)
#pragma unroll
        for (int j = 0; j < 4; j++)
#pragma unroll
            for (int e = 0; e < 4; e++) acc[i][j][e] = 0.f;

    const int S = (Ks + 31) / 32;
    const unsigned aS0 = smem_u32(&As[0][0]);
    const unsigned aS1 = smem_u32(&As[1][0]);
    const unsigned bS0 = smem_u32(&Bs2[0][0]);
    const unsigned bS1 = smem_u32(&Bs2[1][0]);

    for (int pass = 0; pass < 3; ++pass) {
        const unsigned short* Ap = (pass == 2) ? Al : Ah;
        const unsigned short* Bp = (pass == 1) ? Bl : Bh;

        {
#pragma unroll
            for (int i = 0; i < 4; i++) {
                int v = tid + 256 * i;
                int row = v >> 3, ch = v & 7;
                int gk = ch * 4;
                int rem = (bm + row < M) ? (K - gk) : 0;
                int bytes = rem >= 4 ? 8 : 0;
                const void* src = bytes ? (const void*)(Ap + (size_t)(bm + row) * lda + gk)
                                        : (const void*)Ap;
                cp8(aS0 + row * 80 + ch * 8, src, bytes);
            }
#pragma unroll
            for (int i = 0; i < 2; i++) {
                int v = tid + 256 * i;
                int row = v >> 2, ch = v & 3;
                int gk = ch * 8;
                int rem = Ks - gk;
                int bytes = rem >= 8 ? 16 : 0;
                const void* src = bytes ? (const void*)(Bp + (size_t)(bn + row) * ldbt + gk)
                                        : (const void*)Bp;
                cp16(bS0 + row * 80 + ch * 16, src, bytes);
            }
            cp_commit();
        }

        for (int s = 0; s < S; ++s) {
            const int buf = s & 1;
            if (s + 1 < S) {
                int k0 = (s + 1) * 32;
                unsigned aD = buf ? aS0 : aS1;
                unsigned bD = buf ? bS0 : bS1;
#pragma unroll
                for (int i = 0; i < 4; i++) {
                    int v = tid + 256 * i;
                    int row = v >> 3, ch = v & 7;
                    int gk = k0 + ch * 4;
                    int rem = (bm + row < M) ? (K - gk) : 0;
                    int bytes = rem >= 4 ? 8 : 0;
                    const void* src = bytes ? (const void*)(Ap + (size_t)(bm + row) * lda + gk)
                                            : (const void*)Ap;
                    cp8(aD + row * 80 + ch * 8, src, bytes);
                }
#pragma unroll
                for (int i = 0; i < 2; i++) {
                    int v = tid + 256 * i;
                    int row = v >> 2, ch = v & 3;
                    int gk = k0 + ch * 8;
                    int rem = Ks - gk;
                    int bytes = rem >= 8 ? 16 : 0;
                    const void* src = bytes ? (const void*)(Bp + (size_t)(bn + row) * ldbt + gk)
                                            : (const void*)Bp;
                    cp16(bD + row * 80 + ch * 16, src, bytes);
                }
            }
            cp_commit();
            cp_wait1();
            __syncthreads();

#pragma unroll
            for (int kh = 0; kh < 2; kh++) {
                unsigned af[4][4], bfr[4][2];
#pragma unroll
                for (int mt = 0; mt < 4; mt++) {
                    int r = wm0 + mt * 16 + g;
                    int w0 = r * 20 + kh * 8 + t;
                    af[mt][0] = As[buf][w0];
                    af[mt][1] = As[buf][w0 + 160];
                    af[mt][2] = As[buf][w0 + 4];
                    af[mt][3] = As[buf][w0 + 164];
                }
#pragma unroll
                for (int nt = 0; nt < 4; nt++) {
                    int r = wn0 + nt * 8 + g;
                    int w0 = r * 20 + kh * 8 + t;
                    bfr[nt][0] = Bs2[buf][w0];
                    bfr[nt][1] = Bs2[buf][w0 + 4];
                }
#pragma unroll
                for (int mt = 0; mt < 4; mt++)
#pragma unroll
                    for (int nt = 0; nt < 4; nt++)
                        mma16816(acc[mt][nt], af[mt], bfr[nt]);
            }
            __syncthreads();
        }
    }

#pragma unroll
    for (int mt = 0; mt < 4; mt++) {
        int r0 = bm + wm0 + mt * 16 + g;
#pragma unroll
        for (int nt = 0; nt < 4; nt++) {
            int c0 = bn + wn0 + nt * 8 + 2 * t;
#pragma unroll
            for (int e = 0; e < 4; e++) {
                int rr = r0 + (e >> 1) * 8;
                int cc = c0 + (e & 1);
                if (rr < M) {
                    float v = acc[mt][nt][e];
                    float* p = C + (size_t)rr * ldc + cc;
                    if (accflag) {
                        *p += v;
                    } else {
                        v += bias ? bias[cc] : 0.f;
                        if (leakyflag) v = (v >= 0.f) ? v : 0.01f * v;
                        *p = v;
                    }
                }
            }
        }
    }
}

// ---------------- persistent chunked-LSTM scan (round-9 proven version) -------
#define SCAN_NB 128
#define COLS_PB 6

__global__ void __launch_bounds__(256) scan_k(const float* __restrict__ Whh,
                                              int N, int n_chunks)
{
    extern __shared__ float sh[];
    const int tid = threadIdx.x;
    const int lane = tid & 31, warp = tid >> 5;
    const int colBase = blockIdx.x * COLS_PB;
    unsigned target = 0;

    for (int t = 0; t < n_chunks; ++t) {
        if (t == 0) {
            for (int i = tid; i < 16 * HID; i += 256) sh[i] = 0.f;
        } else {
            const float* src = d_hbuf + (size_t)(9 + (t - 1) * 16) * HID;
            for (int i = tid; i < 16 * HID; i += 256) sh[i] = __ldcg(src + i);
        }
        __syncthreads();

        float acc[3][16];
#pragma unroll
        for (int p = 0; p < 3; p++)
#pragma unroll
            for (int r = 0; r < 16; r++) acc[p][r] = 0.f;

        const float* wrow[3];
#pragma unroll
        for (int p = 0; p < 3; p++) {
            int pp = warp * 3 + p;
            int gate = pp / COLS_PB, cl = pp % COLS_PB;
            wrow[p] = Whh + (size_t)(gate * HID + colBase + cl) * HID;
        }
#pragma unroll 4
        for (int it = 0; it < 24; ++it) {
            int f = lane + 32 * it;
            float hreg[16];
#pragma unroll
            for (int r = 0; r < 16; r++) hreg[r] = sh[r * HID + f];
#pragma unroll
            for (int p = 0; p < 3; p++) {
                float w = __ldg(wrow[p] + f);
#pragma unroll
                for (int r = 0; r < 16; r++) acc[p][r] += w * hreg[r];
            }
        }
        __syncthreads();

#pragma unroll
        for (int p = 0; p < 3; p++) {
            int pp = warp * 3 + p;
            int gate = pp / COLS_PB, cl = pp % COLS_PB;
#pragma unroll
            for (int r = 0; r < 16; r++) {
                float v = acc[p][r];
                v += __shfl_down_sync(0xffffffffu, v, 16);
                v += __shfl_down_sync(0xffffffffu, v, 8);
                v += __shfl_down_sync(0xffffffffu, v, 4);
                v += __shfl_down_sync(0xffffffffu, v, 2);
                v += __shfl_down_sync(0xffffffffu, v, 1);
                if (lane == 0) sh[(cl * 4 + gate) * 16 + r] = v;
            }
        }
        __syncthreads();

        if (tid < 16 * COLS_PB) {
            int r = tid & 15, cl = tid >> 4;
            int n = t * 16 + r;
            if (n < N) {
                int col = colBase + cl;
                const float* gq = d_G + (size_t)n * G4;
                float gi = gq[col]        + sh[(cl * 4 + 0) * 16 + r];
                float gf = gq[col + 768]  + sh[(cl * 4 + 1) * 16 + r];
                float gg = gq[col + 1536] + sh[(cl * 4 + 2) * 16 + r];
                float go = gq[col + 2304] + sh[(cl * 4 + 3) * 16 + r];
                float cp = (t == 0) ? 0.f : d_cbuf[(size_t)(9 + n - 16) * HID + col];
                float c2 = sigm(gf) * cp + sigm(gi) * tanhf(gg);
                d_hbuf[(size_t)(9 + n) * HID + col] = sigm(go) * tanhf(c2);
                d_cbuf[(size_t)(9 + n) * HID + col] = c2;
            }
        }
        __threadfence();
        __syncthreads();
        target += gridDim.x;
        if (tid == 0) {
            atomicAdd(&d_bar, 1u);
            while (*((volatile unsigned*)&d_bar) < target) { __nanosleep(20); }
        }
        __syncthreads();
        __threadfence();
    }
}

// ---------------- final LSTM cell epilogue ------------------------------------
__global__ void k_final(float* __restrict__ out, int N, int rev)
{
    int idx = blockIdx.x * blockDim.x + threadIdx.x;
    if (idx >= N * HID) return;
    int n = idx / HID, ch = idx % HID;
    const float* g = d_G + (size_t)n * G4;
    float gi = sigm(g[ch]);
    float gf = sigm(g[ch + 768]);
    float gg = tanhf(g[ch + 1536]);
    float go = sigm(g[ch + 2304]);
    float cp = d_cbuf[(size_t)(n + (rev ? 18 : 0)) * HID + ch];
    float c2 = gf * cp + gi * gg;
    out[(size_t)n * 1536 + (rev ? 768 : 0) + ch] = go * tanhf(c2);
}

// ---------------- host side ---------------------------------------------------
static inline int ceil_div(int a, int b) { return (a + b - 1) / b; }

static void gemm16(int aid, size_t aoff, int lda, int bid, size_t boff, int ldbt,
                   int cid, size_t coff, int ldc, int M, int Nn, int K, int Ks,
                   const float* bias_ext, int bias_id, int acc, int leaky = 0)
{
    dim3 g(Nn / 128, ceil_div(M, 128));
    gemm16_k<<<g, 256>>>(aid, aoff, lda, bid, boff, ldbt, cid, coff, ldc,
                         M, Nn, K, Ks, bias_ext, bias_id, acc, leaky);
}

extern "C" void kernel_launch(void* const* d_in, const int* in_sizes, int n_in,
                              void* d_out, int out_size)
{
    const float* x      = (const float*)d_in[0];
    const int*   lens   = (const int*)d_in[1];
    const float* cw[3]  = {(const float*)d_in[2], (const float*)d_in[4], (const float*)d_in[6]};
    const float* cb[3]  = {(const float*)d_in[3], (const float*)d_in[5], (const float*)d_in[7]};
    const float* W_ih   = (const float*)d_in[8];
    const float* W_hh   = (const float*)d_in[9];
    const float* b_ih   = (const float*)d_in[10];
    const float* b_hh   = (const float*)d_in[11];
    const float* W_ihr  = (const float*)d_in[12];
    const float* W_hhr  = (const float*)d_in[13];
    const float* b_ihr  = (const float*)d_in[14];
    const float* b_hhr  = (const float*)d_in[15];
    float* out = (float*)d_out;

    const int N = out_size / 1536;
    const int n_chunks = (N + 15) / 16;
    const int Ksv[3] = {KSV0, KSV1, KSV2};
    const int ks[3] = {3, 5, 7};

    // setup (5 launches so launches 6-8 are the conv GEMMs for ncu)
    k_init<<<1, 32>>>(lens);
    k_pos<<<ceil_div(N, 256), 256>>>(N);
    k_xpad<<<ceil_div((N + 6) * IDIM, 256), 256>>>(x, N);
    k_split4<<<ceil_div((N + 6) * IDIM / 4, 256), 256>>>(B_XPAD, H_XPAD, (N + 6) * IDIM / 4);
    k_prepw<<<ceil_div(G4 * 1536, 256), 256>>>(W_ih, W_hh, W_ihr, W_hhr,
                                               b_ih, b_hh, b_ihr, b_hhr,
                                               cw[0], cw[1], cw[2]);

    // conv: one tensor GEMM per kernel size; bias + LeakyReLU fused
    for (int c = 0; c < 3; c++) {
        int k = ks[c], p = k / 2, chOff = 256 * c;
        gemm16(H_XPAD, (size_t)(3 - p) * IDIM, IDIM,
               H_CBT, (size_t)c * 256 * CBT_STRIDE, Ksv[c],
               B_XFEAT, (size_t)chOff, HID,
               N, 256, k * IDIM, Ksv[c],
               cb[c], -1, 0, /*leaky=*/1);
    }
    k_pool<<<ceil_div(N * HID, 256), 256>>>(N);
    k_split_xf4<<<ceil_div(N * HID / 4, 256), 256>>>(N * HID / 4);
    k_split4<<<ceil_div(N * HID / 4, 256), 256>>>(B_XPOOL, H_XPOOL, N * HID / 4);

    // scan gates x-part: G = xpool @ W_ih^T + (b_ih + b_hh)
    gemm16(H_XPOOL, 0, HID, H_WIH, 0, HID, B_G, 0, G4, N, G4, HID, HID, 0, B_BSUM, 0);
    k_zero_hc<<<ceil_div(18 * HID, 256), 256>>>(N);
    scan_k<<<SCAN_NB, 256, 16 * HID * sizeof(float)>>>(W_hh, N, n_chunks);
    k_split_h4<<<ceil_div(N * HID / 4, 256), 256>>>(N * HID / 4);

    // forward final cell: one fused K=1536 GEMM ([xfeat|h_prev] @ [Wih|Whh]^T)
    gemm16(H_FZF, 0, 1536, H_WFZ, 0, 1536, B_G, 0, G4, N, G4, 1536, 1536, 0, B_BSUM, 0);
    k_final<<<ceil_div(N * HID, 256), 256>>>(out, N, 0);

    // reverse final cell: one fused K=1536 GEMM ([xfeat|h_next] @ [Wihr|Whhr]^T)
    gemm16(H_FZR, 0, 1536, H_WFZR, 0, 1536, B_G, 0, G4, N, G4, 1536, 1536, 0, B_BSUMR, 0);
    k_final<<<ceil_div(N * HID, 256), 256>>>(out, N, 1);
}